// round 5
// baseline (speedup 1.0000x reference)
#include <cuda_runtime.h>

// SpatialAwareFocalLoss — GB300 sm_103a, round 5.
//  * class-QUARTER split: 4 CTAs per sequence (2 classes each) -> 256 CTAs,
//    so most SMs co-reside 2x 1024-thread CTAs = 64 warps = full warp slots
//    (round-4's 1-CTA/SM capped occupancy at 50%).
//  * __launch_bounds__(1024, 2) + slim registers to guarantee co-residency.
//  * line-binning retained: packed int (cnt + tsum<<16) gate is exact.

static constexpr int S    = 1024;   // SEQ_LEN
static constexpr int NBIN = 262;    // line 0..255 + 2 offset + slack
static constexpr int MAXB = 1024;

__device__ float        g_part[MAXB];
__device__ unsigned int g_cnt = 0;

__global__ __launch_bounds__(1024, 2)
void focal_kernel(const float* __restrict__ pred,
                  const float* __restrict__ target,
                  const int*   __restrict__ token_to_line,
                  float* __restrict__ out,
                  float inv_total, int nblocks)
{
    __shared__ int   s_bin_i[NBIN];  // cnt + (tsum<<16), index = line + 2
    __shared__ float s_bin_f[NBIN];  // this quarter's sigmoid sum per line
    __shared__ float s_red[32];

    const int bid  = blockIdx.x;
    const int b    = bid >> 2;        // sequence
    const int q    = bid & 3;         // class quarter: classes 2q, 2q+1
    const int i    = threadIdx.x;
    const int lane = i & 31, warp = i >> 5;

    if (i < NBIN) { s_bin_i[i] = 0; s_bin_f[i] = 0.0f; }

    const long tok  = (long)b * S + i;
    const long base = tok * 8;

    // issue li early: it gates the atomic phase
    const int li = __ldg(token_to_line + tok);
    const float2 p2 = __ldg((const float2*)(pred + base + q * 2));
    const float4 ta = __ldg((const float4*)(target + base));
    const float4 tb = __ldg((const float4*)(target + base + 4));

    __syncthreads();   // bins zeroed before any atomic lands

    // full-class token target sum (small integer, exact) -> window gate
    const int tint = (int)(ta.x + ta.y + ta.z + ta.w + tb.x + tb.y + tb.z + tb.w);

    // this quarter's two target values
    const float t0 = (q == 0) ? ta.x : (q == 1) ? ta.z : (q == 2) ? tb.x : tb.z;
    const float t1 = (q == 0) ? ta.y : (q == 1) ? ta.w : (q == 2) ? tb.y : tb.w;

    float p[2] = {p2.x, p2.y};
    float t[2] = {t0, t1};

    float sigsum = 0.0f, local = 0.0f;
    #pragma unroll
    for (int c = 0; c < 2; ++c) {
        const float x = p[c];
        const float e = __expf(-fabsf(x));
        const float a = 1.0f / (1.0f + e);        // sigmoid(|x|)
        const float g = e * a;                    // 1 - sigmoid(|x|)
        const float sig  = (x >= 0.0f) ? a : g;
        const float sig1 = (x >= 0.0f) ? g : a;   // 1 - sig
        sigsum += sig;
        const float pt  = (t[c] > 0.5f) ? sig : sig1;
        const float omp = (t[c] > 0.5f) ? sig1 : sig;   // 1 - pt
        const float bce = -__logf(pt);
        const float o2  = omp * omp;
        local += 0.01f * o2 * o2 * bce;           // ALPHA*(1-pt)^GAMMA*bce
    }

    const int self_i = 1 + (tint << 16);
    atomicAdd(&s_bin_i[li + 2], self_i);
    atomicAdd(&s_bin_f[li + 2], sigsum);
    __syncthreads();

    // window lines [li-2, li+2] -> bins [li, li+4]; exclude self
    int   ci   = -self_i;
    float nsig = -sigsum;
    #pragma unroll
    for (int k = 0; k < 5; ++k) {
        ci   += s_bin_i[li + k];
        nsig += s_bin_f[li + k];
    }
    const int cnt  = ci & 0xffff;     // neighbors excluding self
    const int ntgt = ci >> 16;        // exact integer nearby target sum

    if (cnt > 0 && ntgt > 0)
        local += 0.03f * __fdividef(nsig, (float)cnt);

    // block reduction -> one partial per CTA
    #pragma unroll
    for (int o = 16; o > 0; o >>= 1)
        local += __shfl_xor_sync(0xffffffffu, local, o);
    if (lane == 0) s_red[warp] = local;
    __syncthreads();

    if (warp == 0) {
        float v = s_red[lane];
        #pragma unroll
        for (int o = 16; o > 0; o >>= 1)
            v += __shfl_xor_sync(0xffffffffu, v, o);

        unsigned int ticket = 0;
        if (lane == 0) {
            g_part[bid] = v;
            __threadfence();
            ticket = atomicAdd(&g_cnt, 1u) + 1u;
        }
        ticket = __shfl_sync(0xffffffffu, ticket, 0);

        if ((int)ticket == nblocks) {           // last CTA: final reduce
            __threadfence();
            float acc = 0.0f;
            for (int k = lane; k < nblocks; k += 32)
                acc += __ldcg(&g_part[k]);
            #pragma unroll
            for (int o = 16; o > 0; o >>= 1)
                acc += __shfl_xor_sync(0xffffffffu, acc, o);
            if (lane == 0) {
                out[0] = acc * inv_total;
                g_cnt = 0;                      // reset for next graph replay
            }
        }
    }
}

extern "C" void kernel_launch(void* const* d_in, const int* in_sizes, int n_in,
                              void* d_out, int out_size)
{
    const float* pred   = (const float*)d_in[0];
    const float* target = (const float*)d_in[1];
    const int*   lines  = (const int*)d_in[2];
    float* out = (float*)d_out;

    const int BS = in_sizes[2];
    const int B  = BS / S;
    const int nblocks = 4 * B;                 // 4 class-quarters per sequence
    const float inv_total = 1.0f / ((float)BS * 8.0f);

    focal_kernel<<<nblocks, 1024>>>(pred, target, lines, out, inv_total, nblocks);
}